// round 2
// baseline (speedup 1.0000x reference)
#include <cuda_runtime.h>

#define N2V   10000
#define KDIM  256
#define NF    64
#define N1R   8192
#define KH    5

// scratch: s = G @ x  ([8192, 256], 8.4 MB)  — allocation-free __device__ global
__device__ float g_s[N1R * KDIM];

// ---------------------------------------------------------------------------
// Kernel 1: s[i,:] = sum_{k<5} x[qq[5i+k], :]
// (floor(softmax/1000) == 0 identically, so e == G exactly; G has 5 ones/row.)
// 64 threads per row (one float4 each), 4 rows per 256-thread block.
// ---------------------------------------------------------------------------
__global__ __launch_bounds__(256) void gsum_kernel(const float* __restrict__ x,
                                                   const int* __restrict__ qq,
                                                   float* __restrict__ s) {
    const int tid = threadIdx.x;
    const int lr  = tid >> 6;          // local row 0..3
    const int c   = tid & 63;          // float4 column 0..63 (256 floats/row)
    const int i   = blockIdx.x * 4 + lr;

    const int* q = qq + i * KH;
    const int q0 = __ldg(q + 0);
    const int q1 = __ldg(q + 1);
    const int q2 = __ldg(q + 2);
    const int q3 = __ldg(q + 3);
    const int q4 = __ldg(q + 4);

    const float4* x4 = (const float4*)x;   // row stride 64 float4
    float4 a0 = x4[(size_t)q0 * 64 + c];
    float4 a1 = x4[(size_t)q1 * 64 + c];
    float4 a2 = x4[(size_t)q2 * 64 + c];
    float4 a3 = x4[(size_t)q3 * 64 + c];
    float4 a4 = x4[(size_t)q4 * 64 + c];

    float4 r;
    r.x = a0.x + a1.x + a2.x + a3.x + a4.x;
    r.y = a0.y + a1.y + a2.y + a3.y + a4.y;
    r.z = a0.z + a1.z + a2.z + a3.z + a4.z;
    r.w = a0.w + a1.w + a2.w + a3.w + a4.w;

    ((float4*)s)[(size_t)i * 64 + c] = r;
}

// ---------------------------------------------------------------------------
// Kernel 2: out = s @ W + 5*bias   (M=8192, K=256, N=64)
// 1024 CTAs (256 row-tiles x 4 col-tiles) -> 6.92 avg / 7 max CTAs per SM
// => wave-quantization tail ~1%, unlike the 157-CTA layout (tail 2.0x).
// CTA: BM=32 x BN=16, 64 threads, microtile 2 rows x 4 cols.
// ss padded [32][33]: row stride 33 => rg reads hit distinct banks; broadcast
// across cg is free. ws [32][16]: float4 reads within one 64B row.
// ---------------------------------------------------------------------------
__global__ __launch_bounds__(64) void gemm_kernel(const float* __restrict__ s,
                                                  const float* __restrict__ w,
                                                  const float* __restrict__ bias,
                                                  float* __restrict__ out) {
    __shared__ float ss[32][33];
    __shared__ float ws[32][16];

    const int tid = threadIdx.x;
    const int rt  = blockIdx.x >> 2;   // row tile 0..255
    const int ct  = blockIdx.x & 3;    // col tile 0..3
    const int r0  = rt * 32;
    const int c0  = ct * 16;
    const int rg  = tid >> 2;          // 0..15 -> rows rg*2, rg*2+1
    const int cg  = tid & 3;           // 0..3  -> cols cg*4 .. cg*4+3

    float acc[2][4] = {};

    for (int k0 = 0; k0 < KDIM; k0 += 32) {
        // load s tile [32 x 32]: 256 float4, 4 per thread; scalar stores (pad 33)
        #pragma unroll
        for (int j = 0; j < 4; j++) {
            int idx = tid + j * 64;          // 0..255
            int r = idx >> 3, cc = idx & 7;
            float4 v = *(const float4*)(s + (size_t)(r0 + r) * KDIM + k0 + cc * 4);
            ss[r][cc * 4 + 0] = v.x;
            ss[r][cc * 4 + 1] = v.y;
            ss[r][cc * 4 + 2] = v.z;
            ss[r][cc * 4 + 3] = v.w;
        }
        // load w tile [32 x 16]: 128 float4, 2 per thread
        #pragma unroll
        for (int j = 0; j < 2; j++) {
            int idx = tid + j * 64;          // 0..127
            int kk = idx >> 2, cc = idx & 3;
            *(float4*)&ws[kk][cc * 4] =
                *(const float4*)(w + (size_t)(k0 + kk) * NF + c0 + cc * 4);
        }
        __syncthreads();

        #pragma unroll
        for (int kk = 0; kk < 32; kk++) {
            float4 wv = *(const float4*)&ws[kk][cg * 4];
            float x0 = ss[rg * 2 + 0][kk];
            float x1 = ss[rg * 2 + 1][kk];
            acc[0][0] += x0 * wv.x;
            acc[0][1] += x0 * wv.y;
            acc[0][2] += x0 * wv.z;
            acc[0][3] += x0 * wv.w;
            acc[1][0] += x1 * wv.x;
            acc[1][1] += x1 * wv.y;
            acc[1][2] += x1 * wv.z;
            acc[1][3] += x1 * wv.w;
        }
        __syncthreads();
    }

    float4 b = *(const float4*)(bias + c0 + cg * 4);
    #pragma unroll
    for (int m = 0; m < 2; m++) {
        int row = r0 + rg * 2 + m;
        float4 o;
        o.x = acc[m][0] + 5.0f * b.x;
        o.y = acc[m][1] + 5.0f * b.y;
        o.z = acc[m][2] + 5.0f * b.z;
        o.w = acc[m][3] + 5.0f * b.w;
        *(float4*)(out + (size_t)row * NF + c0 + cg * 4) = o;
    }
}

// ---------------------------------------------------------------------------
// Inputs (metadata order):
//   0: x [10000,256] f32, 1: G (unused), 2: weight [256,64] f32,
//   3: a (unused — attention branch is identically zero), 4: bias [64] f32,
//   5: qq [40960] i32, 6: rows (unused)
// output: [8192,64] f32
// ---------------------------------------------------------------------------
extern "C" void kernel_launch(void* const* d_in, const int* in_sizes, int n_in,
                              void* d_out, int out_size) {
    const float* x    = (const float*)d_in[0];
    const float* w    = (const float*)d_in[2];
    const float* bias = (const float*)d_in[4];
    const int*   qq   = (const int*)d_in[5];
    float*       out  = (float*)d_out;

    float* s = nullptr;
    cudaGetSymbolAddress((void**)&s, g_s);

    gsum_kernel<<<N1R / 4, 256>>>(x, qq, s);
    gemm_kernel<<<(N1R / 32) * 4, 64>>>(s, w, bias, out);
}